// round 1
// baseline (speedup 1.0000x reference)
#include <cuda_runtime.h>

#define NN 100000
#define EE 3200000
#define TOT (EE + NN)
#define HH 8
#define CC 16
#define HC 128
#define NEG 0.2f

// Scratch (__device__ globals -- no allocation allowed)
__device__ float    g_h[NN * HC];       // projected features [N, H*C]
__device__ float    g_asrc[NN * HH];    // per-node src logits
__device__ float    g_adst[NN * HH];    // per-node dst logits
__device__ unsigned g_amax[NN * HH];    // segment max (flipped-float encoding)
__device__ float    g_denom[NN * HH];   // segment softmax denominator

__device__ __forceinline__ unsigned flipf(float f) {
    unsigned u = __float_as_uint(f);
    return (u & 0x80000000u) ? ~u : (u | 0x80000000u);
}
__device__ __forceinline__ float unflipf(unsigned u) {
    return __uint_as_float((u & 0x80000000u) ? (u ^ 0x80000000u) : ~u);
}

// ---------------- init: out = bias broadcast, amax/denom zeroed ----------------
__global__ void k_init(float* __restrict__ out, const float* __restrict__ bias) {
    int i = blockIdx.x * blockDim.x + threadIdx.x;
    if (i < NN * HC) out[i] = bias[i & (HC - 1)];
    if (i < NN * HH) { g_amax[i] = 0u; g_denom[i] = 0.0f; }
}

// ---------------- GEMM: g_h = x @ W  (block tile 32 rows x 128 cols) ----------------
__global__ void k_gemm(const float* __restrict__ x, const float* __restrict__ W) {
    __shared__ float sX[32][33];
    __shared__ float sW[32][HC];
    int tid = threadIdx.x;
    int rb = blockIdx.x * 32;
    int c = (tid & 31) * 4;        // 4 contiguous output cols
    int r = (tid >> 5) * 4;        // 4 rows
    float4 acc[4];
#pragma unroll
    for (int rr = 0; rr < 4; rr++) acc[rr] = make_float4(0.f, 0.f, 0.f, 0.f);

    for (int k0 = 0; k0 < 128; k0 += 32) {
        for (int idx = tid; idx < 32 * 32; idx += 256) {
            int i = idx >> 5, j = idx & 31;
            sX[i][j] = x[(rb + i) * 128 + k0 + j];
        }
        for (int idx = tid; idx < 32 * 128; idx += 256) {
            int i = idx >> 7, j = idx & 127;
            sW[i][j] = W[(k0 + i) * 128 + j];
        }
        __syncthreads();
#pragma unroll
        for (int kk = 0; kk < 32; kk++) {
            float4 wv = *(const float4*)&sW[kk][c];
#pragma unroll
            for (int rr = 0; rr < 4; rr++) {
                float xv = sX[r + rr][kk];
                acc[rr].x += xv * wv.x;
                acc[rr].y += xv * wv.y;
                acc[rr].z += xv * wv.z;
                acc[rr].w += xv * wv.w;
            }
        }
        __syncthreads();
    }
#pragma unroll
    for (int rr = 0; rr < 4; rr++)
        *(float4*)&g_h[(rb + r + rr) * HC + c] = acc[rr];
}

// ---------------- per-node attention logits ----------------
__global__ void k_logits(const float* __restrict__ att_src, const float* __restrict__ att_dst) {
    int t = blockIdx.x * blockDim.x + threadIdx.x;
    if (t >= NN * HH) return;
    int n = t >> 3, hh = t & 7;
    const float4* hp = (const float4*)(g_h + n * HC + hh * CC);
    const float4* as = (const float4*)(att_src + hh * CC);
    const float4* ad = (const float4*)(att_dst + hh * CC);
    float s = 0.f, d = 0.f;
#pragma unroll
    for (int i = 0; i < 4; i++) {
        float4 hv = hp[i], a = as[i], b = ad[i];
        s += hv.x * a.x + hv.y * a.y + hv.z * a.z + hv.w * a.w;
        d += hv.x * b.x + hv.y * b.y + hv.z * b.z + hv.w * b.w;
    }
    g_asrc[t] = s;
    g_adst[t] = d;
}

// ---------------- segment max over edges (incl. self loops) ----------------
__global__ void k_max(const int* __restrict__ ei) {
    int e = blockIdx.x * blockDim.x + threadIdx.x;
    if (e >= TOT) return;
    int s, d;
    if (e < EE) { s = ei[e]; d = ei[EE + e]; } else { s = e - EE; d = s; }
    float4 s0 = *(const float4*)&g_asrc[s * 8];
    float4 s1 = *(const float4*)&g_asrc[s * 8 + 4];
    float4 d0 = *(const float4*)&g_adst[d * 8];
    float4 d1 = *(const float4*)&g_adst[d * 8 + 4];
    float a[8] = { s0.x + d0.x, s0.y + d0.y, s0.z + d0.z, s0.w + d0.w,
                   s1.x + d1.x, s1.y + d1.y, s1.z + d1.z, s1.w + d1.w };
#pragma unroll
    for (int i = 0; i < 8; i++) {
        float v = a[i] > 0.f ? a[i] : NEG * a[i];
        atomicMax(&g_amax[d * 8 + i], flipf(v));
    }
}

// ---------------- softmax denominator ----------------
__global__ void k_sum(const int* __restrict__ ei) {
    int e = blockIdx.x * blockDim.x + threadIdx.x;
    if (e >= TOT) return;
    int s, d;
    if (e < EE) { s = ei[e]; d = ei[EE + e]; } else { s = e - EE; d = s; }
    float4 s0 = *(const float4*)&g_asrc[s * 8];
    float4 s1 = *(const float4*)&g_asrc[s * 8 + 4];
    float4 d0 = *(const float4*)&g_adst[d * 8];
    float4 d1 = *(const float4*)&g_adst[d * 8 + 4];
    float a[8] = { s0.x + d0.x, s0.y + d0.y, s0.z + d0.z, s0.w + d0.w,
                   s1.x + d1.x, s1.y + d1.y, s1.z + d1.z, s1.w + d1.w };
#pragma unroll
    for (int i = 0; i < 8; i++) {
        float v = a[i] > 0.f ? a[i] : NEG * a[i];
        float m = unflipf(g_amax[d * 8 + i]);
        atomicAdd(&g_denom[d * 8 + i], __expf(v - m));
    }
}

// ---------------- weighted scatter: warp per edge, float4 red atomics ----------------
__global__ void k_scatter(const int* __restrict__ ei, float* __restrict__ out) {
    int gw = (blockIdx.x * blockDim.x + threadIdx.x) >> 5;
    int lane = threadIdx.x & 31;
    if (gw >= TOT) return;
    int s, d;
    if (gw < EE) { s = ei[gw]; d = ei[EE + gw]; } else { s = gw - EE; d = s; }
    int hh = lane >> 2;
    float a = g_asrc[s * 8 + hh] + g_adst[d * 8 + hh];
    a = a > 0.f ? a : NEG * a;
    float m = unflipf(g_amax[d * 8 + hh]);
    float den = g_denom[d * 8 + hh];
    float w = __expf(a - m) / (den + 1e-16f);
    float4 v = *(const float4*)&g_h[s * HC + lane * 4];
    v.x *= w; v.y *= w; v.z *= w; v.w *= w;
    float* p = out + d * HC + lane * 4;
    asm volatile("red.global.add.v4.f32 [%0], {%1,%2,%3,%4};"
                 :: "l"(p), "f"(v.x), "f"(v.y), "f"(v.z), "f"(v.w)
                 : "memory");
}

extern "C" void kernel_launch(void* const* d_in, const int* in_sizes, int n_in,
                              void* d_out, int out_size) {
    const float* x    = (const float*)d_in[0];
    const int*   ei   = (const int*)d_in[1];
    const float* W    = (const float*)d_in[2];
    const float* as   = (const float*)d_in[3];
    const float* ad   = (const float*)d_in[4];
    const float* bias = (const float*)d_in[5];
    float* out = (float*)d_out;

    k_init   <<<(NN * HC + 255) / 256, 256>>>(out, bias);
    k_gemm   <<<NN / 32, 256>>>(x, W);
    k_logits <<<(NN * HH + 255) / 256, 256>>>(as, ad);
    k_max    <<<(TOT + 255) / 256, 256>>>(ei);
    k_sum    <<<(TOT + 255) / 256, 256>>>(ei);
    {
        long long threads = (long long)TOT * 32;
        int blocks = (int)((threads + 255) / 256);
        k_scatter<<<blocks, 256>>>(ei, out);
    }
}

// round 2
// speedup vs baseline: 2.3263x; 2.3263x over previous
#include <cuda_runtime.h>

#define NN 100000
#define EE 3200000
#define HH 8
#define CC 16
#define HC 128
#define NEG 0.2f

// Scratch (__device__ globals -- no allocation allowed)
__device__ float g_h[NN * HC];        // projected features [N, H*C]
__device__ float g_asrc[NN * HH];     // per-node src logits
__device__ float g_adst[NN * HH];     // per-node dst logits
__device__ int   g_deg[NN];           // in-degree (excl. self loop)
__device__ int   g_cur[NN];           // fill cursors
__device__ int   g_rowptr[NN + 1];    // CSR row pointers (by dst)
__device__ int   g_col[EE];           // CSR column indices (src node per edge)

// ---------------- init: zero degree + cursors ----------------
__global__ void k_init(void) {
    int i = blockIdx.x * blockDim.x + threadIdx.x;
    if (i < NN) { g_deg[i] = 0; g_cur[i] = 0; }
}

// ---------------- GEMM: g_h = x @ W  (block tile 32 rows x 128 cols) ----------------
__global__ void k_gemm(const float* __restrict__ x, const float* __restrict__ W) {
    __shared__ float sX[32][33];
    __shared__ float sW[32][HC];
    int tid = threadIdx.x;
    int rb = blockIdx.x * 32;
    int c = (tid & 31) * 4;
    int r = (tid >> 5) * 4;
    float4 acc[4];
#pragma unroll
    for (int rr = 0; rr < 4; rr++) acc[rr] = make_float4(0.f, 0.f, 0.f, 0.f);

    for (int k0 = 0; k0 < 128; k0 += 32) {
        for (int idx = tid; idx < 32 * 32; idx += 256) {
            int i = idx >> 5, j = idx & 31;
            sX[i][j] = x[(rb + i) * 128 + k0 + j];
        }
        for (int idx = tid; idx < 32 * 128; idx += 256) {
            int i = idx >> 7, j = idx & 127;
            sW[i][j] = W[(k0 + i) * 128 + j];
        }
        __syncthreads();
#pragma unroll
        for (int kk = 0; kk < 32; kk++) {
            float4 wv = *(const float4*)&sW[kk][c];
#pragma unroll
            for (int rr = 0; rr < 4; rr++) {
                float xv = sX[r + rr][kk];
                acc[rr].x += xv * wv.x;
                acc[rr].y += xv * wv.y;
                acc[rr].z += xv * wv.z;
                acc[rr].w += xv * wv.w;
            }
        }
        __syncthreads();
    }
#pragma unroll
    for (int rr = 0; rr < 4; rr++)
        *(float4*)&g_h[(rb + r + rr) * HC + c] = acc[rr];
}

// ---------------- per-node attention logits ----------------
__global__ void k_logits(const float* __restrict__ att_src, const float* __restrict__ att_dst) {
    int t = blockIdx.x * blockDim.x + threadIdx.x;
    if (t >= NN * HH) return;
    int n = t >> 3, hh = t & 7;
    const float4* hp = (const float4*)(g_h + n * HC + hh * CC);
    const float4* as = (const float4*)(att_src + hh * CC);
    const float4* ad = (const float4*)(att_dst + hh * CC);
    float s = 0.f, d = 0.f;
#pragma unroll
    for (int i = 0; i < 4; i++) {
        float4 hv = hp[i], a = as[i], b = ad[i];
        s += hv.x * a.x + hv.y * a.y + hv.z * a.z + hv.w * a.w;
        d += hv.x * b.x + hv.y * b.y + hv.z * b.z + hv.w * b.w;
    }
    g_asrc[t] = s;
    g_adst[t] = d;
}

// ---------------- degree histogram (by dst) ----------------
__global__ void k_deg(const int* __restrict__ ei) {
    int e = blockIdx.x * blockDim.x + threadIdx.x;
    if (e >= EE) return;
    atomicAdd(&g_deg[ei[EE + e]], 1);
}

// ---------------- exclusive prefix scan over degrees (single block) ----------------
__global__ void k_scan(void) {
    __shared__ int ssum[1024];
    const int CH = (NN + 1023) / 1024;  // 98
    int t = threadIdx.x;
    int beg = t * CH;
    int end = beg + CH; if (end > NN) end = NN;
    int sum = 0;
    for (int i = beg; i < end; i++) sum += g_deg[i];
    ssum[t] = sum;
    __syncthreads();
    // Hillis-Steele inclusive scan
    for (int off = 1; off < 1024; off <<= 1) {
        int v = (t >= off) ? ssum[t - off] : 0;
        __syncthreads();
        ssum[t] += v;
        __syncthreads();
    }
    int run = (t == 0) ? 0 : ssum[t - 1];
    for (int i = beg; i < end; i++) {
        int d = g_deg[i];
        g_rowptr[i] = run;
        run += d;
    }
    if (t == 1023) g_rowptr[NN] = ssum[1023];
}

// ---------------- fill CSR ----------------
__global__ void k_fill(const int* __restrict__ ei) {
    int e = blockIdx.x * blockDim.x + threadIdx.x;
    if (e >= EE) return;
    int s = ei[e], d = ei[EE + e];
    int p = atomicAdd(&g_cur[d], 1);
    g_col[g_rowptr[d] + p] = s;
}

// ---------------- fused softmax + aggregation: warp per dst node, no atomics ----------------
__global__ void __launch_bounds__(256) k_agg(float* __restrict__ out,
                                             const float* __restrict__ bias) {
    int i = (blockIdx.x * blockDim.x + threadIdx.x) >> 5;
    if (i >= NN) return;
    int lane = threadIdx.x & 31;
    int hh = lane >> 2;                 // head for this lane's 4 output cols

    float adv = g_adst[i * 8 + hh];

    // self loop contribution
    float a = g_asrc[i * 8 + hh] + adv;
    a = a > 0.f ? a : NEG * a;
    float w = __expf(a);
    float wsum = w;
    float4 hv = *(const float4*)&g_h[i * HC + lane * 4];
    float4 acc = make_float4(w * hv.x, w * hv.y, w * hv.z, w * hv.w);

    int beg = g_rowptr[i], end = g_rowptr[i + 1];
    for (int e = beg; e < end; e += 4) {
        int m = end - e;
        int s0 = __ldg(&g_col[e]);
        int s1 = (m > 1) ? __ldg(&g_col[e + 1]) : s0;
        int s2 = (m > 2) ? __ldg(&g_col[e + 2]) : s0;
        int s3 = (m > 3) ? __ldg(&g_col[e + 3]) : s0;
        float as0 = g_asrc[s0 * 8 + hh];
        float as1 = g_asrc[s1 * 8 + hh];
        float as2 = g_asrc[s2 * 8 + hh];
        float as3 = g_asrc[s3 * 8 + hh];
        float4 h0 = *(const float4*)&g_h[s0 * HC + lane * 4];
        float4 h1 = *(const float4*)&g_h[s1 * HC + lane * 4];
        float4 h2 = *(const float4*)&g_h[s2 * HC + lane * 4];
        float4 h3 = *(const float4*)&g_h[s3 * HC + lane * 4];

        float a0 = as0 + adv; a0 = a0 > 0.f ? a0 : NEG * a0;
        float a1 = as1 + adv; a1 = a1 > 0.f ? a1 : NEG * a1;
        float a2 = as2 + adv; a2 = a2 > 0.f ? a2 : NEG * a2;
        float a3 = as3 + adv; a3 = a3 > 0.f ? a3 : NEG * a3;
        float w0 = __expf(a0);
        float w1 = (m > 1) ? __expf(a1) : 0.f;
        float w2 = (m > 2) ? __expf(a2) : 0.f;
        float w3 = (m > 3) ? __expf(a3) : 0.f;

        wsum += w0 + w1 + w2 + w3;
        acc.x += w0 * h0.x + w1 * h1.x + w2 * h2.x + w3 * h3.x;
        acc.y += w0 * h0.y + w1 * h1.y + w2 * h2.y + w3 * h3.y;
        acc.z += w0 * h0.z + w1 * h1.z + w2 * h2.z + w3 * h3.z;
        acc.w += w0 * h0.w + w1 * h1.w + w2 * h2.w + w3 * h3.w;
    }

    float inv = 1.f / (wsum + 1e-16f);
    float4 bv = *(const float4*)&bias[lane * 4];
    float4 o = make_float4(acc.x * inv + bv.x, acc.y * inv + bv.y,
                           acc.z * inv + bv.z, acc.w * inv + bv.w);
    *(float4*)&out[i * HC + lane * 4] = o;
}

extern "C" void kernel_launch(void* const* d_in, const int* in_sizes, int n_in,
                              void* d_out, int out_size) {
    const float* x    = (const float*)d_in[0];
    const int*   ei   = (const int*)d_in[1];
    const float* W    = (const float*)d_in[2];
    const float* as   = (const float*)d_in[3];
    const float* ad   = (const float*)d_in[4];
    const float* bias = (const float*)d_in[5];
    float* out = (float*)d_out;

    k_init   <<<(NN + 255) / 256, 256>>>();
    k_gemm   <<<NN / 32, 256>>>(x, W);
    k_logits <<<(NN * HH + 255) / 256, 256>>>(as, ad);
    k_deg    <<<(EE + 255) / 256, 256>>>(ei);
    k_scan   <<<1, 1024>>>();
    k_fill   <<<(EE + 255) / 256, 256>>>(ei);
    k_agg    <<<(NN * 32 + 255) / 256, 256>>>(out, bias);
}